// round 15
// baseline (speedup 1.0000x reference)
#include <cuda_runtime.h>
#include <cuda_fp16.h>
#include <cstdint>
#include <math.h>

#define ROWS   8192
#define SEQ    4096
#define DM     1024
#define DI     2048
#define NH     8
#define HD     256
#define NS     64
#define CHK    64
#define NC     64
#define PROJ   5128
#define PROJP  5376
#define OFF_Z  0
#define OFF_X  2048
#define OFF_B  4096
#define OFF_C  4608
#define OFF_DT 5120
#define EPSV   1.1920929e-7f

// ------------------------- scratch (device globals) -------------------------
__device__ __half g_normed[ROWS * DM];
__device__ __half g_proj[(size_t)ROWS * PROJ];
__device__ __half g_x[ROWS * DI];
__device__ __half g_GMh[(size_t)1024 * 4096];
__device__ __half g_Ceh[(size_t)1024 * 4096];
__device__ __half g_Bth[(size_t)1024 * 4096];
__device__ __half g_xTh[(size_t)1024 * 8 * 2048];
__device__ float g_decay[1024];
__device__ __half g_y[ROWS * DI];
__device__ __half g_yn[ROWS * DI];
__device__ __half g_w1tt[(size_t)PROJP * DM];
__device__ __half g_w2tt[(size_t)DM * DI];

// ------------------------- helpers -------------------------
__device__ __forceinline__ float blk_reduce_sum(float v, float* red) {
    int tid = threadIdx.x;
    #pragma unroll
    for (int o = 16; o > 0; o >>= 1) v += __shfl_xor_sync(0xffffffffu, v, o);
    if ((tid & 31) == 0) red[tid >> 5] = v;
    __syncthreads();
    if (tid < 8) {
        float t = red[tid];
        #pragma unroll
        for (int o = 4; o > 0; o >>= 1) t += __shfl_xor_sync(0xffu, t, o);
        if (tid == 0) red[0] = t;
    }
    __syncthreads();
    return red[0];
}

__device__ __forceinline__ float silu_f(float x) {
    return x / (1.f + __expf(-x));
}

__device__ __forceinline__ uint32_t s2u(const void* p) {
    uint32_t a;
    asm("{ .reg .u64 t; cvta.to.shared.u64 t, %1; cvt.u32.u64 %0, t; }"
        : "=r"(a) : "l"(p));
    return a;
}

__device__ __forceinline__ void cp16s(uint32_t d, const void* s) {
    asm volatile("cp.async.cg.shared.global [%0], [%1], 16;\n" :: "r"(d), "l"(s));
}
__device__ __forceinline__ void cp_commit() {
    asm volatile("cp.async.commit_group;\n" ::);
}
template <int N>
__device__ __forceinline__ void cp_wait() {
    asm volatile("cp.async.wait_group %0;\n" :: "n"(N));
}

__device__ __forceinline__ void mma16h(float* c, const uint32_t* a, const uint32_t* b) {
    asm volatile(
        "mma.sync.aligned.m16n8k16.row.col.f32.f16.f16.f32 "
        "{%0,%1,%2,%3},{%4,%5,%6,%7},{%8,%9},{%0,%1,%2,%3};\n"
        : "+f"(c[0]), "+f"(c[1]), "+f"(c[2]), "+f"(c[3])
        : "r"(a[0]), "r"(a[1]), "r"(a[2]), "r"(a[3]), "r"(b[0]), "r"(b[1]));
}

// ------------------------- K0: transpose + fp16 round weights -------------------------
__global__ __launch_bounds__(256) void k_tr(const float* __restrict__ in,
                                            __half* __restrict__ out,
                                            int Kd, int Nin) {
    __shared__ float t[32][33];
    int k0 = blockIdx.x * 32, n0 = blockIdx.y * 32;
    int tx = threadIdx.x & 31, ty = threadIdx.x >> 5;
    #pragma unroll
    for (int i = ty; i < 32; i += 8) {
        int n = n0 + tx;
        t[i][tx] = (n < Nin) ? in[(size_t)(k0 + i) * Nin + n] : 0.f;
    }
    __syncthreads();
    #pragma unroll
    for (int i = ty; i < 32; i += 8)
        out[(size_t)(n0 + i) * Kd + k0 + tx] = __float2half_rn(t[tx][i]);
}

// ------------------------- K1: input RMSNorm (fp16 output) -------------------------
__global__ __launch_bounds__(256) void k_rms_in(const float* __restrict__ hidden,
                                                const float* __restrict__ w) {
    int row = blockIdx.x, tid = threadIdx.x;
    __shared__ float red[8];
    float4 v = ((const float4*)(hidden + (size_t)row * DM))[tid];
    float ss = v.x * v.x + v.y * v.y + v.z * v.z + v.w * v.w;
    ss = blk_reduce_sum(ss, red);
    float sc = rsqrtf(ss * (1.0f / DM) + EPSV);
    float4 wv = ((const float4*)w)[tid];
    __half2 h0 = __floats2half2_rn(v.x * sc * wv.x, v.y * sc * wv.y);
    __half2 h1 = __floats2half2_rn(v.z * sc * wv.z, v.w * sc * wv.w);
    uint2 pk;
    pk.x = *(uint32_t*)&h0;
    pk.y = *(uint32_t*)&h1;
    ((uint2*)(g_normed + (size_t)row * DM))[tid] = pk;
}

// ------------------------- FP16 mma GEMM: BM=BN=128, 128 thr, 3 stages -------------------------
#define HSTR 48
#define A_HALFS (128 * HSTR)
#define B_HALFS (128 * HSTR)
#define STG_HALFS (A_HALFS + B_HALFS)
#define NSTG 3
#define GSMEM (NSTG * STG_HALFS * 2)

__device__ __forceinline__ void fill_stage(const __half* __restrict__ A,
                                           const __half* __restrict__ BT,
                                           __half* __restrict__ sm, int s,
                                           int bm, int bn, int kt, int K, int tid) {
    __half* As = sm + s * STG_HALFS;
    __half* Bs = As + A_HALFS;
    uint32_t ab = s2u(As), bb = s2u(Bs);
    const __half* Ap = A + (size_t)bm * K + kt * 32;
    #pragma unroll
    for (int j = 0; j < 4; j++) {
        int i = tid + 128 * j;
        int row = i >> 2, c = i & 3;
        cp16s(ab + (row * HSTR + c * 8) * 2, Ap + (size_t)row * K + c * 8);
    }
    const __half* Bp = BT + (size_t)bn * K + kt * 32;
    #pragma unroll
    for (int j = 0; j < 4; j++) {
        int i = tid + 128 * j;
        int row = i >> 2, c = i & 3;
        cp16s(bb + (row * HSTR + c * 8) * 2, Bp + (size_t)row * K + c * 8);
    }
}

template <typename OutT>
__global__ __launch_bounds__(128, 2) void gemm_hc(const __half* __restrict__ A,
                                                  const __half* __restrict__ BT,
                                                  const float* __restrict__ R,
                                                  OutT* __restrict__ C,
                                                  int M, int N, int K, int addR,
                                                  int bnoff) {
    extern __shared__ __half smh[];
    int tid = threadIdx.x, lane = tid & 31, warp = tid >> 5;
    int bm = blockIdx.y * 128, bn = (blockIdx.x + bnoff) * 128;
    int wm = (warp >> 1) * 64, wn = (warp & 1) * 64;
    int r = lane >> 2, cc = lane & 3;
    float acc[4][8][4];
    #pragma unroll
    for (int mi = 0; mi < 4; mi++)
        #pragma unroll
        for (int ni = 0; ni < 8; ni++)
            #pragma unroll
            for (int q = 0; q < 4; q++) acc[mi][ni][q] = 0.f;

    int nk = K >> 5;
    #pragma unroll
    for (int s = 0; s < NSTG; s++) {
        fill_stage(A, BT, smh, s, bm, bn, s, K, tid);
        cp_commit();
    }

    int s = 0;
    for (int kt = 0; kt < nk; kt++) {
        cp_wait<NSTG - 1>();
        __syncthreads();
        const __half* As = smh + s * STG_HALFS;
        const __half* Bs = As + A_HALFS;
        const __half* arow = As + (wm + r) * HSTR + 4 * cc;
        const __half* brow = Bs + (wn + r) * HSTR + 4 * cc;
        #pragma unroll
        for (int s16 = 0; s16 < 32; s16 += 16) {
            uint32_t af[4][4];
            #pragma unroll
            for (int mi = 0; mi < 4; mi++) {
                uint2 v0 = *(const uint2*)(arow + mi * 16 * HSTR + s16);
                uint2 v1 = *(const uint2*)(arow + (mi * 16 + 8) * HSTR + s16);
                af[mi][0] = v0.x; af[mi][1] = v1.x;
                af[mi][2] = v0.y; af[mi][3] = v1.y;
            }
            uint32_t bf[8][2];
            #pragma unroll
            for (int ni = 0; ni < 8; ni++) {
                uint2 w = *(const uint2*)(brow + ni * 8 * HSTR + s16);
                bf[ni][0] = w.x; bf[ni][1] = w.y;
            }
            #pragma unroll
            for (int mi = 0; mi < 4; mi++)
                #pragma unroll
                for (int ni = 0; ni < 8; ni++)
                    mma16h(acc[mi][ni], af[mi], bf[ni]);
        }
        __syncthreads();
        if (kt + NSTG < nk) {
            fill_stage(A, BT, smh, s, bm, bn, kt + NSTG, K, tid);
            cp_commit();
        } else {
            cp_commit();
        }
        s = (s == NSTG - 1) ? 0 : s + 1;
    }

    #pragma unroll
    for (int mi = 0; mi < 4; mi++) {
        int row = bm + wm + mi * 16 + r;
        #pragma unroll
        for (int ni = 0; ni < 8; ni++) {
            int col = bn + wn + ni * 8 + 2 * cc;
            if (col < N) {
                size_t o0 = (size_t)row * N + col;
                size_t o1 = (size_t)(row + 8) * N + col;
                if (sizeof(OutT) == 2) {
                    __half2 u0 = __floats2half2_rn(acc[mi][ni][0], acc[mi][ni][1]);
                    __half2 u1 = __floats2half2_rn(acc[mi][ni][2], acc[mi][ni][3]);
                    *(__half2*)((__half*)C + o0) = u0;
                    *(__half2*)((__half*)C + o1) = u1;
                } else {
                    float2 v0 = make_float2(acc[mi][ni][0], acc[mi][ni][1]);
                    float2 v1 = make_float2(acc[mi][ni][2], acc[mi][ni][3]);
                    if (addR) {
                        float2 r0 = *(const float2*)(R + o0);
                        float2 r1 = *(const float2*)(R + o1);
                        v0.x += r0.x; v0.y += r0.y;
                        v1.x += r1.x; v1.y += r1.y;
                    }
                    *(float2*)((float*)C + o0) = v0;
                    *(float2*)((float*)C + o1) = v1;
                }
            }
        }
    }
}

// ------------------------- K3: conv + SiLU + direct xT pack -------------------------
__global__ __launch_bounds__(256) void k_conv(const float* __restrict__ cw,
                                              const float* __restrict__ cb) {
    int h = blockIdx.x;
    int row0 = blockIdx.y * 8;
    int p = threadIdx.x;
    int c = h * HD + p;
    int s0 = row0 & (SEQ - 1);
    int b = row0 >> 12;
    int chn = s0 >> 6;
    int l0 = s0 & 63;
    int bhc = (b * NH + h) * NC + chn;
    float w0 = cw[c * 4 + 0], w1 = cw[c * 4 + 1], w2 = cw[c * 4 + 2], w3 = cw[c * 4 + 3];
    const __half* xp = g_proj + (size_t)row0 * PROJ + OFF_X + c;
    float x0 = (s0 >= 3) ? __half2float(xp[-3 * (int)PROJ]) : 0.f;
    float x1 = (s0 >= 2) ? __half2float(xp[-2 * (int)PROJ]) : 0.f;
    float x2 = (s0 >= 1) ? __half2float(xp[-(int)PROJ]) : 0.f;
    float bias = cb[c];
    __half hv[8];
    #pragma unroll
    for (int k = 0; k < 8; k++) {
        float x3 = __half2float(xp[(size_t)k * PROJ]);
        float acc = bias + w0 * x0 + w1 * x1 + w2 * x2 + w3 * x3;
        __half hs = __float2half_rn(silu_f(acc));
        g_x[(size_t)(row0 + k) * DI + c] = hs;
        hv[k] = hs;
        x0 = x1; x1 = x2; x2 = x3;
    }
    int pt = p >> 5, pi = p & 31;
    __half* outp = g_xTh + ((size_t)bhc * 8 + pt) * 2048 + pi * 64 + l0;
    __half2 a0, a1, a2, a3;
    a0.x = hv[0]; a0.y = hv[1];
    a1.x = hv[2]; a1.y = hv[3];
    a2.x = hv[4]; a2.y = hv[5];
    a3.x = hv[6]; a3.y = hv[7];
    uint4 pk;
    pk.x = *(uint32_t*)&a0; pk.y = *(uint32_t*)&a1;
    pk.z = *(uint32_t*)&a2; pk.w = *(uint32_t*)&a3;
    *(uint4*)outp = pk;
}

// ------------------------- K4a: chunk prep (dt fused; fp16 outputs) -------------------------
__global__ __launch_bounds__(256) void k_chunkprep(const float* __restrict__ A_log,
                                                   const float* __restrict__ wdt,
                                                   const float* __restrict__ bdt) {
    int c = blockIdx.x, h = blockIdx.y, b = blockIdx.z;
    int bhc = (b * NH + h) * NC + c;
    int rbase = b * SEQ + c * CHK;
    __shared__ float Bc[64 * 68];
    __shared__ float Cc[64 * 68];
    __shared__ float lcs[64];
    __shared__ float sdt[64];
    __shared__ float draw[64][8];
    int tid = threadIdx.x, lane = tid & 31, w = tid >> 5;
    float A = -__expf(A_log[h]);

    #pragma unroll
    for (int i = 0; i < 2; i++) {
        int e = tid + 256 * i;
        int l = e >> 3, j = e & 7;
        draw[l][j] = __half2float(g_proj[(size_t)(rbase + l) * PROJ + OFF_DT + j]);
    }
    #pragma unroll
    for (int i = 0; i < 4; i++) {
        int f = (tid + 256 * i) * 4;
        int l = f >> 6, n = f & 63;
        const __half* pr = g_proj + (size_t)(rbase + l) * PROJ;
        uint2 bu = *(const uint2*)(pr + OFF_B + h * NS + n);
        uint2 cu = *(const uint2*)(pr + OFF_C + h * NS + n);
        __half2 b0 = *(__half2*)&bu.x, b1 = *(__half2*)&bu.y;
        __half2 c0 = *(__half2*)&cu.x, c1 = *(__half2*)&cu.y;
        Bc[l * 68 + n + 0] = __half2float(b0.x); Bc[l * 68 + n + 1] = __half2float(b0.y);
        Bc[l * 68 + n + 2] = __half2float(b1.x); Bc[l * 68 + n + 3] = __half2float(b1.y);
        Cc[l * 68 + n + 0] = __half2float(c0.x); Cc[l * 68 + n + 1] = __half2float(c0.y);
        Cc[l * 68 + n + 2] = __half2float(c1.x); Cc[l * 68 + n + 3] = __half2float(c1.y);
    }
    __syncthreads();

    {
        int d0 = h * HD + lane;
        float wv[8][8], bb[8];
        #pragma unroll
        for (int j = 0; j < 8; j++)
            #pragma unroll
            for (int q = 0; q < 8; q++) wv[j][q] = wdt[j * DI + d0 + 32 * q];
        #pragma unroll
        for (int q = 0; q < 8; q++) bb[q] = bdt[d0 + 32 * q];
        #pragma unroll
        for (int rr = 0; rr < 8; rr++) {
            int l = w * 8 + rr;
            float dj[8];
            #pragma unroll
            for (int j = 0; j < 8; j++) dj[j] = draw[l][j];
            float acc = 0.f;
            #pragma unroll
            for (int q = 0; q < 8; q++) {
                float v = bb[q];
                #pragma unroll
                for (int j = 0; j < 8; j++) v += dj[j] * wv[j][q];
                acc += (v > 15.f) ? v : __logf(1.f + __expf(v));
            }
            #pragma unroll
            for (int o = 16; o > 0; o >>= 1) acc += __shfl_xor_sync(0xffffffffu, acc, o);
            if (lane == 0) sdt[l] = acc * (1.0f / HD) * A;
        }
    }
    __syncthreads();
    if (tid == 0) {
        float run = 0.f;
        for (int l = 0; l < 64; l++) { run += sdt[l]; lcs[l] = run; }
    }
    __syncthreads();
    float lcs63 = lcs[63];

    {
        int l = tid >> 2, i0 = (tid & 3) * 16;
        __half* gout = g_GMh + (size_t)bhc * 4096;
        float myl = lcs[l];
        for (int q = 0; q < 16; q++) {
            int i = i0 + q;
            float g = 0.f;
            #pragma unroll
            for (int n = 0; n < 64; n++) g += Cc[l * 68 + n] * Bc[i * 68 + n];
            float m = (i <= l) ? __expf(myl - lcs[i]) : 0.f;
            gout[l * 64 + i] = __float2half_rn(m * g);
        }
    }
    #pragma unroll
    for (int i = 0; i < 4; i++) {
        int f = (tid + 256 * i) * 4;
        int l = f >> 6, n = f & 63;
        float lc = __expf(lcs[l]);
        __half2* cp = (__half2*)(g_Ceh + (size_t)bhc * 4096 + l * 64 + n);
        cp[0] = __floats2half2_rn(Cc[l * 68 + n + 0] * lc, Cc[l * 68 + n + 1] * lc);
        cp[1] = __floats2half2_rn(Cc[l * 68 + n + 2] * lc, Cc[l * 68 + n + 3] * lc);
        float wl = __expf(lcs63 - lcs[l]);
        __half* bt = g_Bth + (size_t)bhc * 4096;
        bt[(n + 0) * 64 + l] = __float2half_rn(Bc[l * 68 + n + 0] * wl);
        bt[(n + 1) * 64 + l] = __float2half_rn(Bc[l * 68 + n + 1] * wl);
        bt[(n + 2) * 64 + l] = __float2half_rn(Bc[l * 68 + n + 2] * wl);
        bt[(n + 3) * 64 + l] = __float2half_rn(Bc[l * 68 + n + 3] * wl);
    }
    if (tid == 0) g_decay[bhc] = __expf(lcs63);
}

// ------------------------- K4b: pipelined fp16 mma chunk scan -------------------------
#define SSH 80
#define SC_BUF (224 * SSH)
#define SC_SMEM ((2 * SC_BUF + 32 * SSH) * 2)

__device__ __forceinline__ void scan_prefetch(int bhc, int pt, uint32_t sbuf, int tid) {
    const __half* gm = g_GMh + (size_t)bhc * 4096;
    const __half* ce = g_Ceh + (size_t)bhc * 4096;
    const __half* bt = g_Bth + (size_t)bhc * 4096;
    const __half* xt = g_xTh + ((size_t)bhc * 8 + pt) * 2048;
    int rl = tid >> 3, cs = (tid & 7) * 8;
    cp16s(sbuf + ((0 + rl) * SSH + cs) * 2, gm + rl * 64 + cs);
    cp16s(sbuf + ((32 + rl) * SSH + cs) * 2, gm + (32 + rl) * 64 + cs);
    cp16s(sbuf + ((64 + rl) * SSH + cs) * 2, ce + rl * 64 + cs);
    cp16s(sbuf + ((96 + rl) * SSH + cs) * 2, ce + (32 + rl) * 64 + cs);
    cp16s(sbuf + ((128 + rl) * SSH + cs) * 2, bt + rl * 64 + cs);
    cp16s(sbuf + ((160 + rl) * SSH + cs) * 2, bt + (32 + rl) * 64 + cs);
    cp16s(sbuf + ((192 + rl) * SSH + cs) * 2, xt + rl * 64 + cs);
}

__device__ __forceinline__ void mm_tile_h(float* accA, float* accB,
                                          const __half* Asm, const __half* Bsm,
                                          int mt, int nt2, int r, int cc) {
    const __half* ap = Asm + (mt * 16 + r) * SSH + 4 * cc;
    const __half* bp0 = Bsm + (nt2 * 8 + r) * SSH + 4 * cc;
    const __half* bp1 = bp0 + 8 * SSH;
    #pragma unroll
    for (int s16 = 0; s16 < 64; s16 += 16) {
        uint2 a0 = *(const uint2*)(ap + s16);
        uint2 a1 = *(const uint2*)(ap + 8 * SSH + s16);
        uint32_t af[4] = {a0.x, a1.x, a0.y, a1.y};
        uint2 b0 = *(const uint2*)(bp0 + s16);
        uint2 b1 = *(const uint2*)(bp1 + s16);
        uint32_t bf0[2] = {b0.x, b0.y};
        uint32_t bf1[2] = {b1.x, b1.y};
        mma16h(accA, af, bf0);
        mma16h(accB, af, bf1);
    }
}

__global__ __launch_bounds__(256) void k_scan() {
    extern __shared__ __half smH[];
    uint32_t sb = s2u(smH);
    __half* hTs = smH + 2 * SC_BUF;
    int tid = threadIdx.x, lane = tid & 31, w = tid >> 5;
    int pt = blockIdx.x, h = blockIdx.y, b = blockIdx.z;
    int p0 = pt * 32, bh = b * NH + h;
    int r = lane >> 2, cc = lane & 3;
    int mt = w & 3, nt2 = (w >> 2) * 2;

    for (int e = tid; e < 32 * SSH; e += 256) hTs[e] = __float2half_rn(0.f);
    float hA[4] = {0.f, 0.f, 0.f, 0.f};
    float hB[4] = {0.f, 0.f, 0.f, 0.f};

    scan_prefetch(bh * NC, pt, sb, tid);
    cp_commit();

    for (int c = 0; c < NC; c++) {
        int bhc = bh * NC + c;
        int buf = c & 1;
        const __half* Bf = smH + buf * SC_BUF;
        cp_wait<0>();
        __syncthreads();
        if (c + 1 < NC) scan_prefetch(bhc + 1, pt, sb + (buf ^ 1) * SC_BUF * 2, tid);
        cp_commit();

        const __half* GMs = Bf;
        const __half* Ces = Bf + 64 * SSH;
        const __half* Bts = Bf + 128 * SSH;
        const __half* xTs = Bf + 192 * SSH;
        float decay = g_decay[bhc];

        float yA[4] = {0.f, 0.f, 0.f, 0.f};
        float yB[4] = {0.f, 0.f, 0.f, 0.f};
        mm_tile_h(yA, yB, GMs, xTs, mt, nt2, r, cc);
        mm_tile_h(yA, yB, Ces, hTs, mt, nt2, r, cc);
        {
            int tok = b * SEQ + c * CHK + mt * 16 + r;
            int col = h * HD + p0 + nt2 * 8 + 2 * cc;
            __half* y0 = g_y + (size_t)tok * DI + col;
            __half* y1 = g_y + (size_t)(tok + 8) * DI + col;
            *(__half2*)(y0)     = __floats2half2_rn(yA[0], yA[1]);
            *(__half2*)(y0 + 8) = __floats2half2_rn(yB[0], yB[1]);
            *(__half2*)(y1)     = __floats2half2_rn(yA[2], yA[3]);
            *(__half2*)(y1 + 8) = __floats2half2_rn(yB[2], yB[3]);
        }
        #pragma unroll
        for (int q = 0; q < 4; q++) { hA[q] *= decay; hB[q] *= decay; }
        mm_tile_h(hA, hB, Bts, xTs, mt, nt2, r, cc);
        __syncthreads();
        {
            int pp0 = nt2 * 8 + 2 * cc;
            int nn = mt * 16 + r;
            hTs[(pp0 + 0) * SSH + nn]     = __float2half_rn(hA[0]);
            hTs[(pp0 + 1) * SSH + nn]     = __float2half_rn(hA[1]);
            hTs[(pp0 + 0) * SSH + nn + 8] = __float2half_rn(hA[2]);
            hTs[(pp0 + 1) * SSH + nn + 8] = __float2half_rn(hA[3]);
            hTs[(pp0 + 8) * SSH + nn]     = __float2half_rn(hB[0]);
            hTs[(pp0 + 9) * SSH + nn]     = __float2half_rn(hB[1]);
            hTs[(pp0 + 8) * SSH + nn + 8] = __float2half_rn(hB[2]);
            hTs[(pp0 + 9) * SSH + nn + 8] = __float2half_rn(hB[3]);
        }
    }
}

// ------------------------- K5: gate + RMSNorm (fp16 output) -------------------------
__global__ __launch_bounds__(256) void k_gate(const float* __restrict__ Dp,
                                              const float* __restrict__ wno) {
    int row = blockIdx.x, tid = threadIdx.x;
    __shared__ float red[8];
    const __half* yr = g_y + (size_t)row * DI;
    const __half* xr = g_x + (size_t)row * DI;
    const __half* zr = g_proj + (size_t)row * PROJ + OFF_Z;
    float vals[8];
    float ss = 0.f;
    #pragma unroll
    for (int k = 0; k < 8; k++) {
        int cidx = tid + 256 * k;
        int hh = cidx >> 8;
        float y = __half2float(yr[cidx]) + __half2float(xr[cidx]) * Dp[hh];
        float z = __half2float(zr[cidx]);
        float v = y * silu_f(z);
        vals[k] = v; ss += v * v;
    }
    ss = blk_reduce_sum(ss, red);
    float sc = rsqrtf(ss * (1.0f / DI) + EPSV);
    __half* outp = g_yn + (size_t)row * DI;
    #pragma unroll
    for (int k = 0; k < 8; k++) {
        int cidx = tid + 256 * k;
        outp[cidx] = __float2half_rn(vals[k] * sc * wno[cidx]);
    }
}

// ------------------------- launch -------------------------
extern "C" void kernel_launch(void* const* d_in, const int* in_sizes, int n_in,
                              void* d_out, int out_size) {
    const float* hidden = (const float*)d_in[0];
    const float* w_norm_in = (const float*)d_in[1];
    const float* w_in_proj = (const float*)d_in[2];
    const float* conv_w = (const float*)d_in[3];
    const float* conv_b = (const float*)d_in[4];
    const float* w_dt = (const float*)d_in[5];
    const float* b_dt = (const float*)d_in[6];
    const float* A_log = (const float*)d_in[7];
    const float* Dp = (const float*)d_in[8];
    const float* w_norm_out = (const float*)d_in[9];
    const float* w_out_proj = (const float*)d_in[10];
    float* out = (float*)d_out;

    __half *p_normed, *p_projh, *p_yn, *p_w1tt, *p_w2tt;
    cudaGetSymbolAddress((void**)&p_normed, g_normed);
    cudaGetSymbolAddress((void**)&p_projh, g_proj);
    cudaGetSymbolAddress((void**)&p_yn, g_yn);
    cudaGetSymbolAddress((void**)&p_w1tt, g_w1tt);
    cudaGetSymbolAddress((void**)&p_w2tt, g_w2tt);

    cudaFuncSetAttribute(k_scan, cudaFuncAttributeMaxDynamicSharedMemorySize, SC_SMEM);
    cudaFuncSetAttribute(gemm_hc<__half>, cudaFuncAttributeMaxDynamicSharedMemorySize, GSMEM);
    cudaFuncSetAttribute(gemm_hc<float>, cudaFuncAttributeMaxDynamicSharedMemorySize, GSMEM);

    static cudaStream_t s2 = nullptr, s3 = nullptr;
    static cudaEvent_t ev_fork, ev_tr, ev_nz, ev_z, ev_cp;
    if (!s2) {
        cudaStreamCreateWithFlags(&s2, cudaStreamNonBlocking);
        cudaStreamCreateWithFlags(&s3, cudaStreamNonBlocking);
        cudaEventCreateWithFlags(&ev_fork, cudaEventDisableTiming);
        cudaEventCreateWithFlags(&ev_tr, cudaEventDisableTiming);
        cudaEventCreateWithFlags(&ev_nz, cudaEventDisableTiming);
        cudaEventCreateWithFlags(&ev_z, cudaEventDisableTiming);
        cudaEventCreateWithFlags(&ev_cp, cudaEventDisableTiming);
    }

    // fork: weight transposes on s2, concurrent with rms_in
    cudaEventRecord(ev_fork, 0);
    cudaStreamWaitEvent(s2, ev_fork, 0);
    k_tr<<<dim3(DM / 32, PROJP / 32), 256, 0, s2>>>(w_in_proj, p_w1tt, DM, PROJ);
    k_tr<<<dim3(DI / 32, DM / 32), 256, 0, s2>>>(w_out_proj, p_w2tt, DI, DM);
    cudaEventRecord(ev_tr, s2);

    k_rms_in<<<ROWS, 256>>>(hidden, w_norm_in);
    cudaStreamWaitEvent(0, ev_tr, 0);

    // gemm1 non-z tiles (x, B, C, dt columns: tiles 16..40)
    gemm_hc<__half><<<dim3(25, ROWS / 128), 128, GSMEM>>>(
        p_normed, p_w1tt, nullptr, p_projh, ROWS, PROJ, DM, 0, 16);
    cudaEventRecord(ev_nz, 0);

    // gemm1 z tiles (0..15) on s2 — overlaps with conv + scan
    cudaStreamWaitEvent(s2, ev_nz, 0);
    gemm_hc<__half><<<dim3(16, ROWS / 128), 128, GSMEM, s2>>>(
        p_normed, p_w1tt, nullptr, p_projh, ROWS, PROJ, DM, 0, 0);
    cudaEventRecord(ev_z, s2);

    // chunkprep on s3 — overlaps with conv
    cudaStreamWaitEvent(s3, ev_nz, 0);
    k_chunkprep<<<dim3(NC, NH, 2), 256, 0, s3>>>(A_log, w_dt, b_dt);
    cudaEventRecord(ev_cp, s3);

    k_conv<<<dim3(NH, ROWS / 8), 256>>>(conv_w, conv_b);
    cudaStreamWaitEvent(0, ev_cp, 0);
    k_scan<<<dim3(8, NH, 2), 256, SC_SMEM>>>();
    cudaStreamWaitEvent(0, ev_z, 0);
    k_gate<<<ROWS, 256>>>(Dp, w_norm_out);
    gemm_hc<float><<<dim3(DM / 128, ROWS / 128), 128, GSMEM>>>(
        p_yn, p_w2tt, hidden, out, ROWS, DM, DI, 1, 0);
}

// round 16
// speedup vs baseline: 1.0959x; 1.0959x over previous
#include <cuda_runtime.h>
#include <cuda_fp16.h>
#include <cstdint>
#include <math.h>

#define ROWS   8192
#define SEQ    4096
#define DM     1024
#define DI     2048
#define NH     8
#define HD     256
#define NS     64
#define CHK    64
#define NC     64
#define PROJ   5128
#define PROJP  5376
#define OFF_Z  0
#define OFF_X  2048
#define OFF_B  4096
#define OFF_C  4608
#define OFF_DT 5120
#define EPSV   1.1920929e-7f

// ------------------------- scratch (device globals) -------------------------
__device__ __half g_normed[ROWS * DM];
__device__ __half g_proj[(size_t)ROWS * PROJ];
__device__ __half g_x[ROWS * DI];
__device__ __half g_GMh[(size_t)1024 * 4096];
__device__ __half g_Ceh[(size_t)1024 * 4096];
__device__ __half g_Bth[(size_t)1024 * 4096];
__device__ __half g_xTh[(size_t)1024 * 8 * 2048];
__device__ float g_decay[1024];
__device__ __half g_y[ROWS * DI];
__device__ __half g_yn[ROWS * DI];
__device__ __half g_w1tt[(size_t)PROJP * DM];
__device__ __half g_w2tt[(size_t)DM * DI];

// ------------------------- helpers -------------------------
__device__ __forceinline__ float blk_reduce_sum(float v, float* red) {
    int tid = threadIdx.x;
    #pragma unroll
    for (int o = 16; o > 0; o >>= 1) v += __shfl_xor_sync(0xffffffffu, v, o);
    if ((tid & 31) == 0) red[tid >> 5] = v;
    __syncthreads();
    if (tid < 8) {
        float t = red[tid];
        #pragma unroll
        for (int o = 4; o > 0; o >>= 1) t += __shfl_xor_sync(0xffu, t, o);
        if (tid == 0) red[0] = t;
    }
    __syncthreads();
    return red[0];
}

__device__ __forceinline__ float silu_f(float x) {
    return x / (1.f + __expf(-x));
}

__device__ __forceinline__ uint32_t s2u(const void* p) {
    uint32_t a;
    asm("{ .reg .u64 t; cvta.to.shared.u64 t, %1; cvt.u32.u64 %0, t; }"
        : "=r"(a) : "l"(p));
    return a;
}

__device__ __forceinline__ void cp16s(uint32_t d, const void* s) {
    asm volatile("cp.async.cg.shared.global [%0], [%1], 16;\n" :: "r"(d), "l"(s));
}
__device__ __forceinline__ void cp_commit() {
    asm volatile("cp.async.commit_group;\n" ::);
}
template <int N>
__device__ __forceinline__ void cp_wait() {
    asm volatile("cp.async.wait_group %0;\n" :: "n"(N));
}

__device__ __forceinline__ void mma16h(float* c, const uint32_t* a, const uint32_t* b) {
    asm volatile(
        "mma.sync.aligned.m16n8k16.row.col.f32.f16.f16.f32 "
        "{%0,%1,%2,%3},{%4,%5,%6,%7},{%8,%9},{%0,%1,%2,%3};\n"
        : "+f"(c[0]), "+f"(c[1]), "+f"(c[2]), "+f"(c[3])
        : "r"(a[0]), "r"(a[1]), "r"(a[2]), "r"(a[3]), "r"(b[0]), "r"(b[1]));
}

// ------------------------- K0: transpose + fp16 round weights -------------------------
__global__ __launch_bounds__(256) void k_tr(const float* __restrict__ in,
                                            __half* __restrict__ out,
                                            int Kd, int Nin) {
    __shared__ float t[32][33];
    int k0 = blockIdx.x * 32, n0 = blockIdx.y * 32;
    int tx = threadIdx.x & 31, ty = threadIdx.x >> 5;
    #pragma unroll
    for (int i = ty; i < 32; i += 8) {
        int n = n0 + tx;
        t[i][tx] = (n < Nin) ? in[(size_t)(k0 + i) * Nin + n] : 0.f;
    }
    __syncthreads();
    #pragma unroll
    for (int i = ty; i < 32; i += 8)
        out[(size_t)(n0 + i) * Kd + k0 + tx] = __float2half_rn(t[tx][i]);
}

// ------------------------- K1: input RMSNorm (fp16 output) -------------------------
__global__ __launch_bounds__(256) void k_rms_in(const float* __restrict__ hidden,
                                                const float* __restrict__ w) {
    int row = blockIdx.x, tid = threadIdx.x;
    __shared__ float red[8];
    float4 v = ((const float4*)(hidden + (size_t)row * DM))[tid];
    float ss = v.x * v.x + v.y * v.y + v.z * v.z + v.w * v.w;
    ss = blk_reduce_sum(ss, red);
    float sc = rsqrtf(ss * (1.0f / DM) + EPSV);
    float4 wv = ((const float4*)w)[tid];
    __half2 h0 = __floats2half2_rn(v.x * sc * wv.x, v.y * sc * wv.y);
    __half2 h1 = __floats2half2_rn(v.z * sc * wv.z, v.w * sc * wv.w);
    uint2 pk;
    pk.x = *(uint32_t*)&h0;
    pk.y = *(uint32_t*)&h1;
    ((uint2*)(g_normed + (size_t)row * DM))[tid] = pk;
}

// ------------------------- FP16 mma GEMM: BM=BN=128, 128 thr, 3 stages -------------------------
#define HSTR 48
#define A_HALFS (128 * HSTR)
#define B_HALFS (128 * HSTR)
#define STG_HALFS (A_HALFS + B_HALFS)
#define NSTG 3
#define GSMEM (NSTG * STG_HALFS * 2)

__device__ __forceinline__ void fill_stage(const __half* __restrict__ A,
                                           const __half* __restrict__ BT,
                                           __half* __restrict__ sm, int s,
                                           int bm, int bn, int kt, int K, int tid) {
    __half* As = sm + s * STG_HALFS;
    __half* Bs = As + A_HALFS;
    uint32_t ab = s2u(As), bb = s2u(Bs);
    const __half* Ap = A + (size_t)bm * K + kt * 32;
    #pragma unroll
    for (int j = 0; j < 4; j++) {
        int i = tid + 128 * j;
        int row = i >> 2, c = i & 3;
        cp16s(ab + (row * HSTR + c * 8) * 2, Ap + (size_t)row * K + c * 8);
    }
    const __half* Bp = BT + (size_t)bn * K + kt * 32;
    #pragma unroll
    for (int j = 0; j < 4; j++) {
        int i = tid + 128 * j;
        int row = i >> 2, c = i & 3;
        cp16s(bb + (row * HSTR + c * 8) * 2, Bp + (size_t)row * K + c * 8);
    }
}

template <typename OutT>
__global__ __launch_bounds__(128, 2) void gemm_hc(const __half* __restrict__ A,
                                                  const __half* __restrict__ BT,
                                                  const float* __restrict__ R,
                                                  OutT* __restrict__ C,
                                                  int M, int N, int K, int addR) {
    extern __shared__ __half smh[];
    int tid = threadIdx.x, lane = tid & 31, warp = tid >> 5;
    int bm = blockIdx.y * 128, bn = blockIdx.x * 128;
    int wm = (warp >> 1) * 64, wn = (warp & 1) * 64;
    int r = lane >> 2, cc = lane & 3;
    float acc[4][8][4];
    #pragma unroll
    for (int mi = 0; mi < 4; mi++)
        #pragma unroll
        for (int ni = 0; ni < 8; ni++)
            #pragma unroll
            for (int q = 0; q < 4; q++) acc[mi][ni][q] = 0.f;

    int nk = K >> 5;
    #pragma unroll
    for (int s = 0; s < NSTG; s++) {
        fill_stage(A, BT, smh, s, bm, bn, s, K, tid);
        cp_commit();
    }

    int s = 0;
    for (int kt = 0; kt < nk; kt++) {
        cp_wait<NSTG - 1>();
        __syncthreads();
        const __half* As = smh + s * STG_HALFS;
        const __half* Bs = As + A_HALFS;
        const __half* arow = As + (wm + r) * HSTR + 4 * cc;
        const __half* brow = Bs + (wn + r) * HSTR + 4 * cc;
        #pragma unroll
        for (int s16 = 0; s16 < 32; s16 += 16) {
            uint32_t af[4][4];
            #pragma unroll
            for (int mi = 0; mi < 4; mi++) {
                uint2 v0 = *(const uint2*)(arow + mi * 16 * HSTR + s16);
                uint2 v1 = *(const uint2*)(arow + (mi * 16 + 8) * HSTR + s16);
                af[mi][0] = v0.x; af[mi][1] = v1.x;
                af[mi][2] = v0.y; af[mi][3] = v1.y;
            }
            uint32_t bf[8][2];
            #pragma unroll
            for (int ni = 0; ni < 8; ni++) {
                uint2 w = *(const uint2*)(brow + ni * 8 * HSTR + s16);
                bf[ni][0] = w.x; bf[ni][1] = w.y;
            }
            #pragma unroll
            for (int mi = 0; mi < 4; mi++)
                #pragma unroll
                for (int ni = 0; ni < 8; ni++)
                    mma16h(acc[mi][ni], af[mi], bf[ni]);
        }
        __syncthreads();
        if (kt + NSTG < nk) {
            fill_stage(A, BT, smh, s, bm, bn, kt + NSTG, K, tid);
            cp_commit();
        } else {
            cp_commit();
        }
        s = (s == NSTG - 1) ? 0 : s + 1;
    }

    #pragma unroll
    for (int mi = 0; mi < 4; mi++) {
        int row = bm + wm + mi * 16 + r;
        #pragma unroll
        for (int ni = 0; ni < 8; ni++) {
            int col = bn + wn + ni * 8 + 2 * cc;
            if (col < N) {
                size_t o0 = (size_t)row * N + col;
                size_t o1 = (size_t)(row + 8) * N + col;
                if (sizeof(OutT) == 2) {
                    __half2 u0 = __floats2half2_rn(acc[mi][ni][0], acc[mi][ni][1]);
                    __half2 u1 = __floats2half2_rn(acc[mi][ni][2], acc[mi][ni][3]);
                    *(__half2*)((__half*)C + o0) = u0;
                    *(__half2*)((__half*)C + o1) = u1;
                } else {
                    float2 v0 = make_float2(acc[mi][ni][0], acc[mi][ni][1]);
                    float2 v1 = make_float2(acc[mi][ni][2], acc[mi][ni][3]);
                    if (addR) {
                        float2 r0 = *(const float2*)(R + o0);
                        float2 r1 = *(const float2*)(R + o1);
                        v0.x += r0.x; v0.y += r0.y;
                        v1.x += r1.x; v1.y += r1.y;
                    }
                    *(float2*)((float*)C + o0) = v0;
                    *(float2*)((float*)C + o1) = v1;
                }
            }
        }
    }
}

// ------------------------- K3: conv + SiLU + direct xT pack -------------------------
__global__ __launch_bounds__(256) void k_conv(const float* __restrict__ cw,
                                              const float* __restrict__ cb) {
    int h = blockIdx.x;
    int row0 = blockIdx.y * 8;
    int p = threadIdx.x;
    int c = h * HD + p;
    int s0 = row0 & (SEQ - 1);
    int b = row0 >> 12;
    int chn = s0 >> 6;
    int l0 = s0 & 63;
    int bhc = (b * NH + h) * NC + chn;
    float w0 = cw[c * 4 + 0], w1 = cw[c * 4 + 1], w2 = cw[c * 4 + 2], w3 = cw[c * 4 + 3];
    const __half* xp = g_proj + (size_t)row0 * PROJ + OFF_X + c;
    float x0 = (s0 >= 3) ? __half2float(xp[-3 * (int)PROJ]) : 0.f;
    float x1 = (s0 >= 2) ? __half2float(xp[-2 * (int)PROJ]) : 0.f;
    float x2 = (s0 >= 1) ? __half2float(xp[-(int)PROJ]) : 0.f;
    float bias = cb[c];
    __half hv[8];
    #pragma unroll
    for (int k = 0; k < 8; k++) {
        float x3 = __half2float(xp[(size_t)k * PROJ]);
        float acc = bias + w0 * x0 + w1 * x1 + w2 * x2 + w3 * x3;
        __half hs = __float2half_rn(silu_f(acc));
        g_x[(size_t)(row0 + k) * DI + c] = hs;
        hv[k] = hs;
        x0 = x1; x1 = x2; x2 = x3;
    }
    int pt = p >> 5, pi = p & 31;
    __half* outp = g_xTh + ((size_t)bhc * 8 + pt) * 2048 + pi * 64 + l0;
    __half2 a0, a1, a2, a3;
    a0.x = hv[0]; a0.y = hv[1];
    a1.x = hv[2]; a1.y = hv[3];
    a2.x = hv[4]; a2.y = hv[5];
    a3.x = hv[6]; a3.y = hv[7];
    uint4 pk;
    pk.x = *(uint32_t*)&a0; pk.y = *(uint32_t*)&a1;
    pk.z = *(uint32_t*)&a2; pk.w = *(uint32_t*)&a3;
    *(uint4*)outp = pk;
}

// ------------------------- K4a: chunk prep (dt fused; fp16 outputs) -------------------------
__global__ __launch_bounds__(256) void k_chunkprep(const float* __restrict__ A_log,
                                                   const float* __restrict__ wdt,
                                                   const float* __restrict__ bdt) {
    int c = blockIdx.x, h = blockIdx.y, b = blockIdx.z;
    int bhc = (b * NH + h) * NC + c;
    int rbase = b * SEQ + c * CHK;
    __shared__ float Bc[64 * 68];
    __shared__ float Cc[64 * 68];
    __shared__ float lcs[64];
    __shared__ float sdt[64];
    __shared__ float draw[64][8];
    int tid = threadIdx.x, lane = tid & 31, w = tid >> 5;
    float A = -__expf(A_log[h]);

    #pragma unroll
    for (int i = 0; i < 2; i++) {
        int e = tid + 256 * i;
        int l = e >> 3, j = e & 7;
        draw[l][j] = __half2float(g_proj[(size_t)(rbase + l) * PROJ + OFF_DT + j]);
    }
    #pragma unroll
    for (int i = 0; i < 4; i++) {
        int f = (tid + 256 * i) * 4;
        int l = f >> 6, n = f & 63;
        const __half* pr = g_proj + (size_t)(rbase + l) * PROJ;
        uint2 bu = *(const uint2*)(pr + OFF_B + h * NS + n);
        uint2 cu = *(const uint2*)(pr + OFF_C + h * NS + n);
        __half2 b0 = *(__half2*)&bu.x, b1 = *(__half2*)&bu.y;
        __half2 c0 = *(__half2*)&cu.x, c1 = *(__half2*)&cu.y;
        Bc[l * 68 + n + 0] = __half2float(b0.x); Bc[l * 68 + n + 1] = __half2float(b0.y);
        Bc[l * 68 + n + 2] = __half2float(b1.x); Bc[l * 68 + n + 3] = __half2float(b1.y);
        Cc[l * 68 + n + 0] = __half2float(c0.x); Cc[l * 68 + n + 1] = __half2float(c0.y);
        Cc[l * 68 + n + 2] = __half2float(c1.x); Cc[l * 68 + n + 3] = __half2float(c1.y);
    }
    __syncthreads();

    {
        int d0 = h * HD + lane;
        float wv[8][8], bb[8];
        #pragma unroll
        for (int j = 0; j < 8; j++)
            #pragma unroll
            for (int q = 0; q < 8; q++) wv[j][q] = wdt[j * DI + d0 + 32 * q];
        #pragma unroll
        for (int q = 0; q < 8; q++) bb[q] = bdt[d0 + 32 * q];
        #pragma unroll
        for (int rr = 0; rr < 8; rr++) {
            int l = w * 8 + rr;
            float dj[8];
            #pragma unroll
            for (int j = 0; j < 8; j++) dj[j] = draw[l][j];
            float acc = 0.f;
            #pragma unroll
            for (int q = 0; q < 8; q++) {
                float v = bb[q];
                #pragma unroll
                for (int j = 0; j < 8; j++) v += dj[j] * wv[j][q];
                acc += (v > 15.f) ? v : __logf(1.f + __expf(v));
            }
            #pragma unroll
            for (int o = 16; o > 0; o >>= 1) acc += __shfl_xor_sync(0xffffffffu, acc, o);
            if (lane == 0) sdt[l] = acc * (1.0f / HD) * A;
        }
    }
    __syncthreads();
    if (tid == 0) {
        float run = 0.f;
        for (int l = 0; l < 64; l++) { run += sdt[l]; lcs[l] = run; }
    }
    __syncthreads();
    float lcs63 = lcs[63];

    {
        int l = tid >> 2, i0 = (tid & 3) * 16;
        __half* gout = g_GMh + (size_t)bhc * 4096;
        float myl = lcs[l];
        for (int q = 0; q < 16; q++) {
            int i = i0 + q;
            float g = 0.f;
            #pragma unroll
            for (int n = 0; n < 64; n++) g += Cc[l * 68 + n] * Bc[i * 68 + n];
            float m = (i <= l) ? __expf(myl - lcs[i]) : 0.f;
            gout[l * 64 + i] = __float2half_rn(m * g);
        }
    }
    #pragma unroll
    for (int i = 0; i < 4; i++) {
        int f = (tid + 256 * i) * 4;
        int l = f >> 6, n = f & 63;
        float lc = __expf(lcs[l]);
        __half2* cp = (__half2*)(g_Ceh + (size_t)bhc * 4096 + l * 64 + n);
        cp[0] = __floats2half2_rn(Cc[l * 68 + n + 0] * lc, Cc[l * 68 + n + 1] * lc);
        cp[1] = __floats2half2_rn(Cc[l * 68 + n + 2] * lc, Cc[l * 68 + n + 3] * lc);
        float wl = __expf(lcs63 - lcs[l]);
        __half* bt = g_Bth + (size_t)bhc * 4096;
        bt[(n + 0) * 64 + l] = __float2half_rn(Bc[l * 68 + n + 0] * wl);
        bt[(n + 1) * 64 + l] = __float2half_rn(Bc[l * 68 + n + 1] * wl);
        bt[(n + 2) * 64 + l] = __float2half_rn(Bc[l * 68 + n + 2] * wl);
        bt[(n + 3) * 64 + l] = __float2half_rn(Bc[l * 68 + n + 3] * wl);
    }
    if (tid == 0) g_decay[bhc] = __expf(lcs63);
}

// ------------------------- K4b: pipelined fp16 mma chunk scan (512 thr) -------------------------
#define SSH 80
#define SC_BUF (224 * SSH)
#define SC_SMEM ((2 * SC_BUF + 32 * SSH) * 2)

__device__ __forceinline__ void scan_prefetch(int bhc, int pt, uint32_t sbuf, int tid) {
    const __half* gm = g_GMh + (size_t)bhc * 4096;
    const __half* ce = g_Ceh + (size_t)bhc * 4096;
    const __half* bt = g_Bth + (size_t)bhc * 4096;
    const __half* xt = g_xTh + ((size_t)bhc * 8 + pt) * 2048;
    int rl = tid >> 3, cs = (tid & 7) * 8;      // rl 0..63 with 512 threads
    cp16s(sbuf + ((0 + rl) * SSH + cs) * 2, gm + rl * 64 + cs);
    cp16s(sbuf + ((64 + rl) * SSH + cs) * 2, ce + rl * 64 + cs);
    cp16s(sbuf + ((128 + rl) * SSH + cs) * 2, bt + rl * 64 + cs);
    if (tid < 256)
        cp16s(sbuf + ((192 + rl) * SSH + cs) * 2, xt + rl * 64 + cs);
}

// single 16x8 output tile: acc += A[mt tile] @ B[nt tile]^T over K=64
__device__ __forceinline__ void mm_tile1(float* acc,
                                         const __half* Asm, const __half* Bsm,
                                         int mt, int nt, int r, int cc) {
    const __half* ap = Asm + (mt * 16 + r) * SSH + 4 * cc;
    const __half* bp = Bsm + (nt * 8 + r) * SSH + 4 * cc;
    #pragma unroll
    for (int s16 = 0; s16 < 64; s16 += 16) {
        uint2 a0 = *(const uint2*)(ap + s16);
        uint2 a1 = *(const uint2*)(ap + 8 * SSH + s16);
        uint32_t af[4] = {a0.x, a1.x, a0.y, a1.y};
        uint2 b0 = *(const uint2*)(bp + s16);
        uint32_t bf[2] = {b0.x, b0.y};
        mma16h(acc, af, bf);
    }
}

__global__ __launch_bounds__(512) void k_scan() {
    extern __shared__ __half smH[];
    uint32_t sb = s2u(smH);
    __half* hTs = smH + 2 * SC_BUF;
    int tid = threadIdx.x, lane = tid & 31, w = tid >> 5;
    int pt = blockIdx.x, h = blockIdx.y, b = blockIdx.z;
    int p0 = pt * 32, bh = b * NH + h;
    int r = lane >> 2, cc = lane & 3;
    int mt = w & 3, nt = w >> 2;                 // 16 warps: 4 m-tiles x 4 n-tiles

    for (int e = tid; e < 32 * SSH; e += 512) hTs[e] = __float2half_rn(0.f);
    float hA[4] = {0.f, 0.f, 0.f, 0.f};

    scan_prefetch(bh * NC, pt, sb, tid);
    cp_commit();

    for (int c = 0; c < NC; c++) {
        int bhc = bh * NC + c;
        int buf = c & 1;
        const __half* Bf = smH + buf * SC_BUF;
        cp_wait<0>();
        __syncthreads();
        if (c + 1 < NC) scan_prefetch(bhc + 1, pt, sb + (buf ^ 1) * SC_BUF * 2, tid);
        cp_commit();

        const __half* GMs = Bf;
        const __half* Ces = Bf + 64 * SSH;
        const __half* Bts = Bf + 128 * SSH;
        const __half* xTs = Bf + 192 * SSH;
        float decay = g_decay[bhc];

        float yA[4] = {0.f, 0.f, 0.f, 0.f};
        mm_tile1(yA, GMs, xTs, mt, nt, r, cc);
        mm_tile1(yA, Ces, hTs, mt, nt, r, cc);
        {
            int tok = b * SEQ + c * CHK + mt * 16 + r;
            int col = h * HD + p0 + nt * 8 + 2 * cc;
            __half* y0 = g_y + (size_t)tok * DI + col;
            __half* y1 = g_y + (size_t)(tok + 8) * DI + col;
            *(__half2*)(y0) = __floats2half2_rn(yA[0], yA[1]);
            *(__half2*)(y1) = __floats2half2_rn(yA[2], yA[3]);
        }
        #pragma unroll
        for (int q = 0; q < 4; q++) hA[q] *= decay;
        mm_tile1(hA, Bts, xTs, mt, nt, r, cc);
        __syncthreads();
        {
            int pp0 = nt * 8 + 2 * cc;
            int nn = mt * 16 + r;
            hTs[(pp0 + 0) * SSH + nn]     = __float2half_rn(hA[0]);
            hTs[(pp0 + 1) * SSH + nn]     = __float2half_rn(hA[1]);
            hTs[(pp0 + 0) * SSH + nn + 8] = __float2half_rn(hA[2]);
            hTs[(pp0 + 1) * SSH + nn + 8] = __float2half_rn(hA[3]);
        }
    }
}

// ------------------------- K5: gate + RMSNorm (fp16 output) -------------------------
__global__ __launch_bounds__(256) void k_gate(const float* __restrict__ Dp,
                                              const float* __restrict__ wno) {
    int row = blockIdx.x, tid = threadIdx.x;
    __shared__ float red[8];
    const __half* yr = g_y + (size_t)row * DI;
    const __half* xr = g_x + (size_t)row * DI;
    const __half* zr = g_proj + (size_t)row * PROJ + OFF_Z;
    float vals[8];
    float ss = 0.f;
    #pragma unroll
    for (int k = 0; k < 8; k++) {
        int cidx = tid + 256 * k;
        int hh = cidx >> 8;
        float y = __half2float(yr[cidx]) + __half2float(xr[cidx]) * Dp[hh];
        float z = __half2float(zr[cidx]);
        float v = y * silu_f(z);
        vals[k] = v; ss += v * v;
    }
    ss = blk_reduce_sum(ss, red);
    float sc = rsqrtf(ss * (1.0f / DI) + EPSV);
    __half* outp = g_yn + (size_t)row * DI;
    #pragma unroll
    for (int k = 0; k < 8; k++) {
        int cidx = tid + 256 * k;
        outp[cidx] = __float2half_rn(vals[k] * sc * wno[cidx]);
    }
}

// ------------------------- launch -------------------------
extern "C" void kernel_launch(void* const* d_in, const int* in_sizes, int n_in,
                              void* d_out, int out_size) {
    const float* hidden = (const float*)d_in[0];
    const float* w_norm_in = (const float*)d_in[1];
    const float* w_in_proj = (const float*)d_in[2];
    const float* conv_w = (const float*)d_in[3];
    const float* conv_b = (const float*)d_in[4];
    const float* w_dt = (const float*)d_in[5];
    const float* b_dt = (const float*)d_in[6];
    const float* A_log = (const float*)d_in[7];
    const float* Dp = (const float*)d_in[8];
    const float* w_norm_out = (const float*)d_in[9];
    const float* w_out_proj = (const float*)d_in[10];
    float* out = (float*)d_out;

    __half *p_normed, *p_projh, *p_yn, *p_w1tt, *p_w2tt;
    cudaGetSymbolAddress((void**)&p_normed, g_normed);
    cudaGetSymbolAddress((void**)&p_projh, g_proj);
    cudaGetSymbolAddress((void**)&p_yn, g_yn);
    cudaGetSymbolAddress((void**)&p_w1tt, g_w1tt);
    cudaGetSymbolAddress((void**)&p_w2tt, g_w2tt);

    cudaFuncSetAttribute(k_scan, cudaFuncAttributeMaxDynamicSharedMemorySize, SC_SMEM);
    cudaFuncSetAttribute(gemm_hc<__half>, cudaFuncAttributeMaxDynamicSharedMemorySize, GSMEM);
    cudaFuncSetAttribute(gemm_hc<float>, cudaFuncAttributeMaxDynamicSharedMemorySize, GSMEM);

    static cudaStream_t s2 = nullptr;
    static cudaEvent_t ev_fork, ev_tr, ev_g1, ev_cp;
    if (!s2) {
        cudaStreamCreateWithFlags(&s2, cudaStreamNonBlocking);
        cudaEventCreateWithFlags(&ev_fork, cudaEventDisableTiming);
        cudaEventCreateWithFlags(&ev_tr, cudaEventDisableTiming);
        cudaEventCreateWithFlags(&ev_g1, cudaEventDisableTiming);
        cudaEventCreateWithFlags(&ev_cp, cudaEventDisableTiming);
    }

    // fork: weight transposes run on s2 concurrently with rms_in
    cudaEventRecord(ev_fork, 0);
    cudaStreamWaitEvent(s2, ev_fork, 0);
    k_tr<<<dim3(DM / 32, PROJP / 32), 256, 0, s2>>>(w_in_proj, p_w1tt, DM, PROJ);
    k_tr<<<dim3(DI / 32, DM / 32), 256, 0, s2>>>(w_out_proj, p_w2tt, DI, DM);
    cudaEventRecord(ev_tr, s2);

    k_rms_in<<<ROWS, 256>>>(hidden, w_norm_in);
    cudaStreamWaitEvent(0, ev_tr, 0);
    gemm_hc<__half><<<dim3(41, ROWS / 128), 128, GSMEM>>>(
        p_normed, p_w1tt, nullptr, p_projh, ROWS, PROJ, DM, 0);

    // fork: chunkprep on s2 concurrently with conv
    cudaEventRecord(ev_g1, 0);
    cudaStreamWaitEvent(s2, ev_g1, 0);
    k_chunkprep<<<dim3(NC, NH, 2), 256, 0, s2>>>(A_log, w_dt, b_dt);
    cudaEventRecord(ev_cp, s2);

    k_conv<<<dim3(NH, ROWS / 8), 256>>>(conv_w, conv_b);
    cudaStreamWaitEvent(0, ev_cp, 0);
    k_scan<<<dim3(8, NH, 2), 512, SC_SMEM>>>();
    k_gate<<<ROWS, 256>>>(Dp, w_norm_out);
    gemm_hc<float><<<dim3(DM / 128, ROWS / 128), 128, GSMEM>>>(
        p_yn, p_w2tt, hidden, out, ROWS, DM, DI, 1);
}

// round 17
// speedup vs baseline: 1.1154x; 1.0177x over previous
#include <cuda_runtime.h>
#include <cuda_fp16.h>
#include <cstdint>
#include <math.h>

#define ROWS   8192
#define SEQ    4096
#define DM     1024
#define DI     2048
#define NH     8
#define HD     256
#define NS     64
#define CHK    64
#define NC     64
#define PROJ   5128
#define PROJP  5376
#define OFF_Z  0
#define OFF_X  2048
#define OFF_B  4096
#define OFF_C  4608
#define OFF_DT 5120
#define EPSV   1.1920929e-7f

// ------------------------- scratch (device globals) -------------------------
__device__ __half g_normed[ROWS * DM];
__device__ __half g_proj[(size_t)ROWS * PROJ];
__device__ __half g_x[ROWS * DI];
__device__ __half g_GMh[(size_t)1024 * 4096];
__device__ __half g_Ceh[(size_t)1024 * 4096];
__device__ __half g_Bth[(size_t)1024 * 4096];
__device__ __half g_xTh[(size_t)1024 * 8 * 2048];
__device__ float g_decay[1024];
__device__ __half g_y[ROWS * DI];
__device__ __half g_yn[ROWS * DI];
__device__ __half g_w1tt[(size_t)PROJP * DM];
__device__ __half g_w2tt[(size_t)DM * DI];

// ------------------------- helpers -------------------------
__device__ __forceinline__ float blk_reduce_sum(float v, float* red) {
    int tid = threadIdx.x;
    #pragma unroll
    for (int o = 16; o > 0; o >>= 1) v += __shfl_xor_sync(0xffffffffu, v, o);
    if ((tid & 31) == 0) red[tid >> 5] = v;
    __syncthreads();
    if (tid < 8) {
        float t = red[tid];
        #pragma unroll
        for (int o = 4; o > 0; o >>= 1) t += __shfl_xor_sync(0xffu, t, o);
        if (tid == 0) red[0] = t;
    }
    __syncthreads();
    return red[0];
}

__device__ __forceinline__ float silu_f(float x) {
    return x / (1.f + __expf(-x));
}

__device__ __forceinline__ uint32_t s2u(const void* p) {
    uint32_t a;
    asm("{ .reg .u64 t; cvta.to.shared.u64 t, %1; cvt.u32.u64 %0, t; }"
        : "=r"(a) : "l"(p));
    return a;
}

__device__ __forceinline__ void cp16s(uint32_t d, const void* s) {
    asm volatile("cp.async.cg.shared.global [%0], [%1], 16;\n" :: "r"(d), "l"(s));
}
__device__ __forceinline__ void cp_commit() {
    asm volatile("cp.async.commit_group;\n" ::);
}
template <int N>
__device__ __forceinline__ void cp_wait() {
    asm volatile("cp.async.wait_group %0;\n" :: "n"(N));
}

__device__ __forceinline__ void mma16h(float* c, const uint32_t* a, const uint32_t* b) {
    asm volatile(
        "mma.sync.aligned.m16n8k16.row.col.f32.f16.f16.f32 "
        "{%0,%1,%2,%3},{%4,%5,%6,%7},{%8,%9},{%0,%1,%2,%3};\n"
        : "+f"(c[0]), "+f"(c[1]), "+f"(c[2]), "+f"(c[3])
        : "r"(a[0]), "r"(a[1]), "r"(a[2]), "r"(a[3]), "r"(b[0]), "r"(b[1]));
}

// ------------------------- K0: transpose + fp16 round weights -------------------------
__global__ __launch_bounds__(256) void k_tr(const float* __restrict__ in,
                                            __half* __restrict__ out,
                                            int Kd, int Nin) {
    __shared__ float t[32][33];
    int k0 = blockIdx.x * 32, n0 = blockIdx.y * 32;
    int tx = threadIdx.x & 31, ty = threadIdx.x >> 5;
    #pragma unroll
    for (int i = ty; i < 32; i += 8) {
        int n = n0 + tx;
        t[i][tx] = (n < Nin) ? in[(size_t)(k0 + i) * Nin + n] : 0.f;
    }
    __syncthreads();
    #pragma unroll
    for (int i = ty; i < 32; i += 8)
        out[(size_t)(n0 + i) * Kd + k0 + tx] = __float2half_rn(t[tx][i]);
}

// ------------------------- K1: input RMSNorm (fp16 output) -------------------------
__global__ __launch_bounds__(256) void k_rms_in(const float* __restrict__ hidden,
                                                const float* __restrict__ w) {
    int row = blockIdx.x, tid = threadIdx.x;
    __shared__ float red[8];
    float4 v = ((const float4*)(hidden + (size_t)row * DM))[tid];
    float ss = v.x * v.x + v.y * v.y + v.z * v.z + v.w * v.w;
    ss = blk_reduce_sum(ss, red);
    float sc = rsqrtf(ss * (1.0f / DM) + EPSV);
    float4 wv = ((const float4*)w)[tid];
    __half2 h0 = __floats2half2_rn(v.x * sc * wv.x, v.y * sc * wv.y);
    __half2 h1 = __floats2half2_rn(v.z * sc * wv.z, v.w * sc * wv.w);
    uint2 pk;
    pk.x = *(uint32_t*)&h0;
    pk.y = *(uint32_t*)&h1;
    ((uint2*)(g_normed + (size_t)row * DM))[tid] = pk;
}

// ------------------------- FP16 mma GEMM: BM=BN=128, 128 thr, 3 stages, 3 CTAs/SM -------------------------
#define HSTR 48
#define A_HALFS (128 * HSTR)
#define B_HALFS (128 * HSTR)
#define STG_HALFS (A_HALFS + B_HALFS)
#define NSTG 3
#define GSMEM (NSTG * STG_HALFS * 2)

__device__ __forceinline__ void fill_stage(const __half* __restrict__ A,
                                           const __half* __restrict__ BT,
                                           __half* __restrict__ sm, int s,
                                           int bm, int bn, int kt, int K, int tid) {
    __half* As = sm + s * STG_HALFS;
    __half* Bs = As + A_HALFS;
    uint32_t ab = s2u(As), bb = s2u(Bs);
    const __half* Ap = A + (size_t)bm * K + kt * 32;
    #pragma unroll
    for (int j = 0; j < 4; j++) {
        int i = tid + 128 * j;
        int row = i >> 2, c = i & 3;
        cp16s(ab + (row * HSTR + c * 8) * 2, Ap + (size_t)row * K + c * 8);
    }
    const __half* Bp = BT + (size_t)bn * K + kt * 32;
    #pragma unroll
    for (int j = 0; j < 4; j++) {
        int i = tid + 128 * j;
        int row = i >> 2, c = i & 3;
        cp16s(bb + (row * HSTR + c * 8) * 2, Bp + (size_t)row * K + c * 8);
    }
}

template <typename OutT>
__global__ __launch_bounds__(128, 3) void gemm_hc(const __half* __restrict__ A,
                                                  const __half* __restrict__ BT,
                                                  const float* __restrict__ R,
                                                  OutT* __restrict__ C,
                                                  int M, int N, int K, int addR) {
    extern __shared__ __half smh[];
    int tid = threadIdx.x, lane = tid & 31, warp = tid >> 5;
    int bm = blockIdx.y * 128, bn = blockIdx.x * 128;
    int wm = (warp >> 1) * 64, wn = (warp & 1) * 64;
    int r = lane >> 2, cc = lane & 3;
    float acc[4][8][4];
    #pragma unroll
    for (int mi = 0; mi < 4; mi++)
        #pragma unroll
        for (int ni = 0; ni < 8; ni++)
            #pragma unroll
            for (int q = 0; q < 4; q++) acc[mi][ni][q] = 0.f;

    int nk = K >> 5;
    #pragma unroll
    for (int s = 0; s < NSTG; s++) {
        fill_stage(A, BT, smh, s, bm, bn, s, K, tid);
        cp_commit();
    }

    int s = 0;
    for (int kt = 0; kt < nk; kt++) {
        cp_wait<NSTG - 1>();
        __syncthreads();
        const __half* As = smh + s * STG_HALFS;
        const __half* Bs = As + A_HALFS;
        const __half* arow = As + (wm + r) * HSTR + 4 * cc;
        const __half* brow = Bs + (wn + r) * HSTR + 4 * cc;
        #pragma unroll
        for (int s16 = 0; s16 < 32; s16 += 16) {
            uint32_t af[4][4];
            #pragma unroll
            for (int mi = 0; mi < 4; mi++) {
                uint2 v0 = *(const uint2*)(arow + mi * 16 * HSTR + s16);
                uint2 v1 = *(const uint2*)(arow + (mi * 16 + 8) * HSTR + s16);
                af[mi][0] = v0.x; af[mi][1] = v1.x;
                af[mi][2] = v0.y; af[mi][3] = v1.y;
            }
            uint32_t bf[8][2];
            #pragma unroll
            for (int ni = 0; ni < 8; ni++) {
                uint2 w = *(const uint2*)(brow + ni * 8 * HSTR + s16);
                bf[ni][0] = w.x; bf[ni][1] = w.y;
            }
            #pragma unroll
            for (int mi = 0; mi < 4; mi++)
                #pragma unroll
                for (int ni = 0; ni < 8; ni++)
                    mma16h(acc[mi][ni], af[mi], bf[ni]);
        }
        __syncthreads();
        if (kt + NSTG < nk) {
            fill_stage(A, BT, smh, s, bm, bn, kt + NSTG, K, tid);
            cp_commit();
        } else {
            cp_commit();
        }
        s = (s == NSTG - 1) ? 0 : s + 1;
    }

    #pragma unroll
    for (int mi = 0; mi < 4; mi++) {
        int row = bm + wm + mi * 16 + r;
        #pragma unroll
        for (int ni = 0; ni < 8; ni++) {
            int col = bn + wn + ni * 8 + 2 * cc;
            if (col < N) {
                size_t o0 = (size_t)row * N + col;
                size_t o1 = (size_t)(row + 8) * N + col;
                if (sizeof(OutT) == 2) {
                    __half2 u0 = __floats2half2_rn(acc[mi][ni][0], acc[mi][ni][1]);
                    __half2 u1 = __floats2half2_rn(acc[mi][ni][2], acc[mi][ni][3]);
                    *(__half2*)((__half*)C + o0) = u0;
                    *(__half2*)((__half*)C + o1) = u1;
                } else {
                    float2 v0 = make_float2(acc[mi][ni][0], acc[mi][ni][1]);
                    float2 v1 = make_float2(acc[mi][ni][2], acc[mi][ni][3]);
                    if (addR) {
                        float2 r0 = *(const float2*)(R + o0);
                        float2 r1 = *(const float2*)(R + o1);
                        v0.x += r0.x; v0.y += r0.y;
                        v1.x += r1.x; v1.y += r1.y;
                    }
                    *(float2*)((float*)C + o0) = v0;
                    *(float2*)((float*)C + o1) = v1;
                }
            }
        }
    }
}

// ------------------------- K3: conv + SiLU + direct xT pack -------------------------
__global__ __launch_bounds__(256) void k_conv(const float* __restrict__ cw,
                                              const float* __restrict__ cb) {
    int h = blockIdx.x;
    int row0 = blockIdx.y * 8;
    int p = threadIdx.x;
    int c = h * HD + p;
    int s0 = row0 & (SEQ - 1);
    int b = row0 >> 12;
    int chn = s0 >> 6;
    int l0 = s0 & 63;
    int bhc = (b * NH + h) * NC + chn;
    float w0 = cw[c * 4 + 0], w1 = cw[c * 4 + 1], w2 = cw[c * 4 + 2], w3 = cw[c * 4 + 3];
    const __half* xp = g_proj + (size_t)row0 * PROJ + OFF_X + c;
    float x0 = (s0 >= 3) ? __half2float(xp[-3 * (int)PROJ]) : 0.f;
    float x1 = (s0 >= 2) ? __half2float(xp[-2 * (int)PROJ]) : 0.f;
    float x2 = (s0 >= 1) ? __half2float(xp[-(int)PROJ]) : 0.f;
    float bias = cb[c];
    __half hv[8];
    #pragma unroll
    for (int k = 0; k < 8; k++) {
        float x3 = __half2float(xp[(size_t)k * PROJ]);
        float acc = bias + w0 * x0 + w1 * x1 + w2 * x2 + w3 * x3;
        __half hs = __float2half_rn(silu_f(acc));
        g_x[(size_t)(row0 + k) * DI + c] = hs;
        hv[k] = hs;
        x0 = x1; x1 = x2; x2 = x3;
    }
    int pt = p >> 5, pi = p & 31;
    __half* outp = g_xTh + ((size_t)bhc * 8 + pt) * 2048 + pi * 64 + l0;
    __half2 a0, a1, a2, a3;
    a0.x = hv[0]; a0.y = hv[1];
    a1.x = hv[2]; a1.y = hv[3];
    a2.x = hv[4]; a2.y = hv[5];
    a3.x = hv[6]; a3.y = hv[7];
    uint4 pk;
    pk.x = *(uint32_t*)&a0; pk.y = *(uint32_t*)&a1;
    pk.z = *(uint32_t*)&a2; pk.w = *(uint32_t*)&a3;
    *(uint4*)outp = pk;
}

// ------------------------- K4a: chunk prep (dt fused; fp16 outputs) -------------------------
__global__ __launch_bounds__(256) void k_chunkprep(const float* __restrict__ A_log,
                                                   const float* __restrict__ wdt,
                                                   const float* __restrict__ bdt) {
    int c = blockIdx.x, h = blockIdx.y, b = blockIdx.z;
    int bhc = (b * NH + h) * NC + c;
    int rbase = b * SEQ + c * CHK;
    __shared__ float Bc[64 * 68];
    __shared__ float Cc[64 * 68];
    __shared__ float lcs[64];
    __shared__ float sdt[64];
    __shared__ float draw[64][8];
    int tid = threadIdx.x, lane = tid & 31, w = tid >> 5;
    float A = -__expf(A_log[h]);

    #pragma unroll
    for (int i = 0; i < 2; i++) {
        int e = tid + 256 * i;
        int l = e >> 3, j = e & 7;
        draw[l][j] = __half2float(g_proj[(size_t)(rbase + l) * PROJ + OFF_DT + j]);
    }
    #pragma unroll
    for (int i = 0; i < 4; i++) {
        int f = (tid + 256 * i) * 4;
        int l = f >> 6, n = f & 63;
        const __half* pr = g_proj + (size_t)(rbase + l) * PROJ;
        uint2 bu = *(const uint2*)(pr + OFF_B + h * NS + n);
        uint2 cu = *(const uint2*)(pr + OFF_C + h * NS + n);
        __half2 b0 = *(__half2*)&bu.x, b1 = *(__half2*)&bu.y;
        __half2 c0 = *(__half2*)&cu.x, c1 = *(__half2*)&cu.y;
        Bc[l * 68 + n + 0] = __half2float(b0.x); Bc[l * 68 + n + 1] = __half2float(b0.y);
        Bc[l * 68 + n + 2] = __half2float(b1.x); Bc[l * 68 + n + 3] = __half2float(b1.y);
        Cc[l * 68 + n + 0] = __half2float(c0.x); Cc[l * 68 + n + 1] = __half2float(c0.y);
        Cc[l * 68 + n + 2] = __half2float(c1.x); Cc[l * 68 + n + 3] = __half2float(c1.y);
    }
    __syncthreads();

    {
        int d0 = h * HD + lane;
        float wv[8][8], bb[8];
        #pragma unroll
        for (int j = 0; j < 8; j++)
            #pragma unroll
            for (int q = 0; q < 8; q++) wv[j][q] = wdt[j * DI + d0 + 32 * q];
        #pragma unroll
        for (int q = 0; q < 8; q++) bb[q] = bdt[d0 + 32 * q];
        #pragma unroll
        for (int rr = 0; rr < 8; rr++) {
            int l = w * 8 + rr;
            float dj[8];
            #pragma unroll
            for (int j = 0; j < 8; j++) dj[j] = draw[l][j];
            float acc = 0.f;
            #pragma unroll
            for (int q = 0; q < 8; q++) {
                float v = bb[q];
                #pragma unroll
                for (int j = 0; j < 8; j++) v += dj[j] * wv[j][q];
                acc += (v > 15.f) ? v : __logf(1.f + __expf(v));
            }
            #pragma unroll
            for (int o = 16; o > 0; o >>= 1) acc += __shfl_xor_sync(0xffffffffu, acc, o);
            if (lane == 0) sdt[l] = acc * (1.0f / HD) * A;
        }
    }
    __syncthreads();
    if (tid == 0) {
        float run = 0.f;
        for (int l = 0; l < 64; l++) { run += sdt[l]; lcs[l] = run; }
    }
    __syncthreads();
    float lcs63 = lcs[63];

    {
        int l = tid >> 2, i0 = (tid & 3) * 16;
        __half* gout = g_GMh + (size_t)bhc * 4096;
        float myl = lcs[l];
        for (int q = 0; q < 16; q++) {
            int i = i0 + q;
            float g = 0.f;
            #pragma unroll
            for (int n = 0; n < 64; n++) g += Cc[l * 68 + n] * Bc[i * 68 + n];
            float m = (i <= l) ? __expf(myl - lcs[i]) : 0.f;
            gout[l * 64 + i] = __float2half_rn(m * g);
        }
    }
    #pragma unroll
    for (int i = 0; i < 4; i++) {
        int f = (tid + 256 * i) * 4;
        int l = f >> 6, n = f & 63;
        float lc = __expf(lcs[l]);
        __half2* cp = (__half2*)(g_Ceh + (size_t)bhc * 4096 + l * 64 + n);
        cp[0] = __floats2half2_rn(Cc[l * 68 + n + 0] * lc, Cc[l * 68 + n + 1] * lc);
        cp[1] = __floats2half2_rn(Cc[l * 68 + n + 2] * lc, Cc[l * 68 + n + 3] * lc);
        float wl = __expf(lcs63 - lcs[l]);
        __half* bt = g_Bth + (size_t)bhc * 4096;
        bt[(n + 0) * 64 + l] = __float2half_rn(Bc[l * 68 + n + 0] * wl);
        bt[(n + 1) * 64 + l] = __float2half_rn(Bc[l * 68 + n + 1] * wl);
        bt[(n + 2) * 64 + l] = __float2half_rn(Bc[l * 68 + n + 2] * wl);
        bt[(n + 3) * 64 + l] = __float2half_rn(Bc[l * 68 + n + 3] * wl);
    }
    if (tid == 0) g_decay[bhc] = __expf(lcs63);
}

// ------------------------- K4b: pipelined fp16 mma chunk scan (512 thr) -------------------------
#define SSH 80
#define SC_BUF (224 * SSH)
#define SC_SMEM ((2 * SC_BUF + 32 * SSH) * 2)

__device__ __forceinline__ void scan_prefetch(int bhc, int pt, uint32_t sbuf, int tid) {
    const __half* gm = g_GMh + (size_t)bhc * 4096;
    const __half* ce = g_Ceh + (size_t)bhc * 4096;
    const __half* bt = g_Bth + (size_t)bhc * 4096;
    const __half* xt = g_xTh + ((size_t)bhc * 8 + pt) * 2048;
    int rl = tid >> 3, cs = (tid & 7) * 8;
    cp16s(sbuf + ((0 + rl) * SSH + cs) * 2, gm + rl * 64 + cs);
    cp16s(sbuf + ((64 + rl) * SSH + cs) * 2, ce + rl * 64 + cs);
    cp16s(sbuf + ((128 + rl) * SSH + cs) * 2, bt + rl * 64 + cs);
    if (tid < 256)
        cp16s(sbuf + ((192 + rl) * SSH + cs) * 2, xt + rl * 64 + cs);
}

__device__ __forceinline__ void mm_tile1(float* acc,
                                         const __half* Asm, const __half* Bsm,
                                         int mt, int nt, int r, int cc) {
    const __half* ap = Asm + (mt * 16 + r) * SSH + 4 * cc;
    const __half* bp = Bsm + (nt * 8 + r) * SSH + 4 * cc;
    #pragma unroll
    for (int s16 = 0; s16 < 64; s16 += 16) {
        uint2 a0 = *(const uint2*)(ap + s16);
        uint2 a1 = *(const uint2*)(ap + 8 * SSH + s16);
        uint32_t af[4] = {a0.x, a1.x, a0.y, a1.y};
        uint2 b0 = *(const uint2*)(bp + s16);
        uint32_t bf[2] = {b0.x, b0.y};
        mma16h(acc, af, bf);
    }
}

__global__ __launch_bounds__(512) void k_scan() {
    extern __shared__ __half smH[];
    uint32_t sb = s2u(smH);
    __half* hTs = smH + 2 * SC_BUF;
    int tid = threadIdx.x, lane = tid & 31, w = tid >> 5;
    int pt = blockIdx.x, h = blockIdx.y, b = blockIdx.z;
    int p0 = pt * 32, bh = b * NH + h;
    int r = lane >> 2, cc = lane & 3;
    int mt = w & 3, nt = w >> 2;

    for (int e = tid; e < 32 * SSH; e += 512) hTs[e] = __float2half_rn(0.f);
    float hA[4] = {0.f, 0.f, 0.f, 0.f};

    scan_prefetch(bh * NC, pt, sb, tid);
    cp_commit();

    for (int c = 0; c < NC; c++) {
        int bhc = bh * NC + c;
        int buf = c & 1;
        const __half* Bf = smH + buf * SC_BUF;
        cp_wait<0>();
        __syncthreads();
        if (c + 1 < NC) scan_prefetch(bhc + 1, pt, sb + (buf ^ 1) * SC_BUF * 2, tid);
        cp_commit();

        const __half* GMs = Bf;
        const __half* Ces = Bf + 64 * SSH;
        const __half* Bts = Bf + 128 * SSH;
        const __half* xTs = Bf + 192 * SSH;
        float decay = g_decay[bhc];

        float yA[4] = {0.f, 0.f, 0.f, 0.f};
        mm_tile1(yA, GMs, xTs, mt, nt, r, cc);
        mm_tile1(yA, Ces, hTs, mt, nt, r, cc);
        {
            int tok = b * SEQ + c * CHK + mt * 16 + r;
            int col = h * HD + p0 + nt * 8 + 2 * cc;
            __half* y0 = g_y + (size_t)tok * DI + col;
            __half* y1 = g_y + (size_t)(tok + 8) * DI + col;
            *(__half2*)(y0) = __floats2half2_rn(yA[0], yA[1]);
            *(__half2*)(y1) = __floats2half2_rn(yA[2], yA[3]);
        }
        #pragma unroll
        for (int q = 0; q < 4; q++) hA[q] *= decay;
        mm_tile1(hA, Bts, xTs, mt, nt, r, cc);
        __syncthreads();
        {
            int pp0 = nt * 8 + 2 * cc;
            int nn = mt * 16 + r;
            hTs[(pp0 + 0) * SSH + nn]     = __float2half_rn(hA[0]);
            hTs[(pp0 + 1) * SSH + nn]     = __float2half_rn(hA[1]);
            hTs[(pp0 + 0) * SSH + nn + 8] = __float2half_rn(hA[2]);
            hTs[(pp0 + 1) * SSH + nn + 8] = __float2half_rn(hA[3]);
        }
    }
}

// ------------------------- K5: gate + RMSNorm (fp16 output) -------------------------
__global__ __launch_bounds__(256) void k_gate(const float* __restrict__ Dp,
                                              const float* __restrict__ wno) {
    int row = blockIdx.x, tid = threadIdx.x;
    __shared__ float red[8];
    const __half* yr = g_y + (size_t)row * DI;
    const __half* xr = g_x + (size_t)row * DI;
    const __half* zr = g_proj + (size_t)row * PROJ + OFF_Z;
    float vals[8];
    float ss = 0.f;
    #pragma unroll
    for (int k = 0; k < 8; k++) {
        int cidx = tid + 256 * k;
        int hh = cidx >> 8;
        float y = __half2float(yr[cidx]) + __half2float(xr[cidx]) * Dp[hh];
        float z = __half2float(zr[cidx]);
        float v = y * silu_f(z);
        vals[k] = v; ss += v * v;
    }
    ss = blk_reduce_sum(ss, red);
    float sc = rsqrtf(ss * (1.0f / DI) + EPSV);
    __half* outp = g_yn + (size_t)row * DI;
    #pragma unroll
    for (int k = 0; k < 8; k++) {
        int cidx = tid + 256 * k;
        outp[cidx] = __float2half_rn(vals[k] * sc * wno[cidx]);
    }
}

// ------------------------- launch -------------------------
extern "C" void kernel_launch(void* const* d_in, const int* in_sizes, int n_in,
                              void* d_out, int out_size) {
    const float* hidden = (const float*)d_in[0];
    const float* w_norm_in = (const float*)d_in[1];
    const float* w_in_proj = (const float*)d_in[2];
    const float* conv_w = (const float*)d_in[3];
    const float* conv_b = (const float*)d_in[4];
    const float* w_dt = (const float*)d_in[5];
    const float* b_dt = (const float*)d_in[6];
    const float* A_log = (const float*)d_in[7];
    const float* Dp = (const float*)d_in[8];
    const float* w_norm_out = (const float*)d_in[9];
    const float* w_out_proj = (const float*)d_in[10];
    float* out = (float*)d_out;

    __half *p_normed, *p_projh, *p_yn, *p_w1tt, *p_w2tt;
    cudaGetSymbolAddress((void**)&p_normed, g_normed);
    cudaGetSymbolAddress((void**)&p_projh, g_proj);
    cudaGetSymbolAddress((void**)&p_yn, g_yn);
    cudaGetSymbolAddress((void**)&p_w1tt, g_w1tt);
    cudaGetSymbolAddress((void**)&p_w2tt, g_w2tt);

    cudaFuncSetAttribute(k_scan, cudaFuncAttributeMaxDynamicSharedMemorySize, SC_SMEM);
    cudaFuncSetAttribute(gemm_hc<__half>, cudaFuncAttributeMaxDynamicSharedMemorySize, GSMEM);
    cudaFuncSetAttribute(gemm_hc<float>, cudaFuncAttributeMaxDynamicSharedMemorySize, GSMEM);

    static cudaStream_t s2 = nullptr;
    static cudaEvent_t ev_fork, ev_tr, ev_g1, ev_cp;
    if (!s2) {
        cudaStreamCreateWithFlags(&s2, cudaStreamNonBlocking);
        cudaEventCreateWithFlags(&ev_fork, cudaEventDisableTiming);
        cudaEventCreateWithFlags(&ev_tr, cudaEventDisableTiming);
        cudaEventCreateWithFlags(&ev_g1, cudaEventDisableTiming);
        cudaEventCreateWithFlags(&ev_cp, cudaEventDisableTiming);
    }

    cudaEventRecord(ev_fork, 0);
    cudaStreamWaitEvent(s2, ev_fork, 0);
    k_tr<<<dim3(DM / 32, PROJP / 32), 256, 0, s2>>>(w_in_proj, p_w1tt, DM, PROJ);
    k_tr<<<dim3(DI / 32, DM / 32), 256, 0, s2>>>(w_out_proj, p_w2tt, DI, DM);
    cudaEventRecord(ev_tr, s2);

    k_rms_in<<<ROWS, 256>>>(hidden, w_norm_in);
    cudaStreamWaitEvent(0, ev_tr, 0);
    gemm_hc<__half><<<dim3(41, ROWS / 128), 128, GSMEM>>>(
        p_normed, p_w1tt, nullptr, p_projh, ROWS, PROJ, DM, 0);

    cudaEventRecord(ev_g1, 0);
    cudaStreamWaitEvent(s2, ev_g1, 0);
    k_chunkprep<<<dim3(NC, NH, 2), 256, 0, s2>>>(A_log, w_dt, b_dt);
    cudaEventRecord(ev_cp, s2);

    k_conv<<<dim3(NH, ROWS / 8), 256>>>(conv_w, conv_b);
    cudaStreamWaitEvent(0, ev_cp, 0);
    k_scan<<<dim3(8, NH, 2), 512, SC_SMEM>>>();
    k_gate<<<ROWS, 256>>>(Dp, w_norm_out);
    gemm_hc<float><<<dim3(DM / 128, ROWS / 128), 128, GSMEM>>>(
        p_yn, p_w2tt, hidden, out, ROWS, DM, DI, 1);
}